// round 1
// baseline (speedup 1.0000x reference)
#include <cuda_runtime.h>
#include <cuda_bf16.h>
#include <cstddef>

// Problem constants (from reference): B=64, S=512, D=768, max_sents=20.
#define BB 64
#define SS 512
#define DD 768
#define MS 20          // segments kept (id == 20 is discarded)
#define DC 256         // D-chunk per block
#define NT 128         // threads per block (each owns a float2 -> 256 floats)
#define UNR 8          // S-loop unroll (MLP)

__global__ __launch_bounds__(NT)
void aspire_pool_kernel(const float* __restrict__ hidden,
                        const int* __restrict__ sent_ids,
                        float* __restrict__ out)
{
    __shared__ float acc[MS * DC];
    __shared__ int   ids[SS];
    __shared__ int   cnt[MS];

    const int b = blockIdx.y;     // batch
    const int c = blockIdx.x;     // D-chunk index (0..2)
    const int t = threadIdx.x;

    // zero accumulators / counts
    #pragma unroll
    for (int i = t; i < MS * DC; i += NT) acc[i] = 0.0f;
    if (t < MS) cnt[t] = 0;
    __syncthreads();

    // preload sent ids for this batch + histogram counts (smem atomics)
    const int* sb = sent_ids + (size_t)b * SS;
    for (int s = t; s < SS; s += NT) {
        int id = sb[s];
        ids[s] = id;
        if (id < MS) atomicAdd(&cnt[id], 1);
    }
    __syncthreads();

    // main accumulation: stream 512 rows of this (batch, chunk)
    const float* hb = hidden + (size_t)b * SS * DD + (size_t)c * DC + (size_t)t * 2;
    const int col = t * 2;

    for (int s0 = 0; s0 < SS; s0 += UNR) {
        float2 v[UNR];
        int    id[UNR];
        #pragma unroll
        for (int u = 0; u < UNR; u++) {
            id[u] = ids[s0 + u];
            v[u]  = *reinterpret_cast<const float2*>(hb + (size_t)(s0 + u) * DD);
        }
        #pragma unroll
        for (int u = 0; u < UNR; u++) {
            if (id[u] < MS) {
                float2* p = reinterpret_cast<float2*>(&acc[id[u] * DC + col]);
                float2 a = *p;
                a.x += v[u].x;
                a.y += v[u].y;
                *p = a;
            }
        }
    }
    __syncthreads();

    // epilogue
    float* doc   = out;                       // [B, D]
    float* sreps = out + (size_t)BB * DD;     // [B, MS, D]

    // doc CLS rep = hidden[b, 0, :]
    {
        float2 v = *reinterpret_cast<const float2*>(
            hidden + (size_t)b * SS * DD + (size_t)c * DC + col);
        *reinterpret_cast<float2*>(doc + (size_t)b * DD + (size_t)c * DC + col) = v;
    }

    // sent reps = acc / max(count, 1)
    #pragma unroll
    for (int k = 0; k < MS; k++) {
        float inv = 1.0f / fmaxf((float)cnt[k], 1.0f);
        float2 a = *reinterpret_cast<float2*>(&acc[k * DC + col]);
        a.x *= inv;
        a.y *= inv;
        *reinterpret_cast<float2*>(
            sreps + ((size_t)b * MS + k) * DD + (size_t)c * DC + col) = a;
    }
}

extern "C" void kernel_launch(void* const* d_in, const int* in_sizes, int n_in,
                              void* d_out, int out_size)
{
    const float* hidden   = (const float*)d_in[0];
    const int*   sent_ids = (const int*)d_in[1];
    float*       out      = (float*)d_out;

    dim3 grid(DD / DC, BB);   // (3, 64)
    aspire_pool_kernel<<<grid, NT>>>(hidden, sent_ids, out);
}

// round 2
// speedup vs baseline: 2.1958x; 2.1958x over previous
#include <cuda_runtime.h>
#include <cuda_bf16.h>
#include <cstddef>

// Problem constants: B=64, S=512, D=768, max_sents=20 (id==20 discarded).
#define BB 64
#define SS 512
#define DD 768
#define MS 20
#define DC 256          // D-chunk per block
#define NT 128          // threads per accumulate block (float2 each -> 256 floats)
#define NSPLIT 4        // S-split across blocks
#define ROWS (SS / NSPLIT)   // 128 rows per block
#define UNR 8

// Scratch: segment sums [B, MS, D] (3.93 MB). Static device array (no alloc).
__device__ float g_sums[BB * MS * DD];

// ---------------------------------------------------------------- zero sums
__global__ __launch_bounds__(512)
void zero_sums_kernel()
{
    int i = blockIdx.x * 512 + threadIdx.x;
    float4* p = reinterpret_cast<float4*>(g_sums);
    // BB*MS*DD/4 = 245760 float4s
    if (i < (BB * MS * DD) / 4) p[i] = make_float4(0.f, 0.f, 0.f, 0.f);
}

// ------------------------------------------------------------- accumulate
__global__ __launch_bounds__(NT)
void accum_kernel(const float* __restrict__ hidden,
                  const int* __restrict__ sent_ids)
{
    __shared__ float acc[MS * DC];
    __shared__ int   ids[ROWS];
    __shared__ int   cnt[MS];     // local per-block segment presence/count

    const int c   = blockIdx.x;   // D-chunk (0..2)
    const int b   = blockIdx.y;   // batch
    const int sp  = blockIdx.z;   // S-split (0..3)
    const int t   = threadIdx.x;
    const int s_base = sp * ROWS;

    #pragma unroll
    for (int i = t; i < MS * DC; i += NT) acc[i] = 0.0f;
    if (t < MS) cnt[t] = 0;
    __syncthreads();

    const int* sb = sent_ids + (size_t)b * SS + s_base;
    if (t < ROWS) {
        int id = sb[t];
        ids[t] = id;
        if (id < MS) atomicAdd(&cnt[id], 1);
    }
    __syncthreads();

    const int col = t * 2;
    const float* hb = hidden + (size_t)b * SS * DD + (size_t)s_base * DD
                             + (size_t)c * DC + col;

    for (int s0 = 0; s0 < ROWS; s0 += UNR) {
        float2 v[UNR];
        int    id[UNR];
        #pragma unroll
        for (int u = 0; u < UNR; u++) {
            id[u] = ids[s0 + u];
            v[u]  = *reinterpret_cast<const float2*>(hb + (size_t)(s0 + u) * DD);
        }
        #pragma unroll
        for (int u = 0; u < UNR; u++) {
            if (id[u] < MS) {
                float2* p = reinterpret_cast<float2*>(&acc[id[u] * DC + col]);
                float2 a = *p;
                a.x += v[u].x;
                a.y += v[u].y;
                *p = a;
            }
        }
    }
    __syncthreads();

    // flush partial sums to global with REDG (skip segments absent locally)
    float* gs = g_sums + ((size_t)b * MS) * DD + (size_t)c * DC + col;
    #pragma unroll
    for (int k = 0; k < MS; k++) {
        if (cnt[k] > 0) {
            atomicAdd(&gs[(size_t)k * DD + 0], acc[k * DC + col + 0]);
            atomicAdd(&gs[(size_t)k * DD + 1], acc[k * DC + col + 1]);
        }
    }
}

// --------------------------------------------------------------- finalize
__global__ __launch_bounds__(384)
void finalize_kernel(const float* __restrict__ hidden,
                     const int* __restrict__ sent_ids,
                     float* __restrict__ out)
{
    __shared__ int cnt[MS];
    const int b = blockIdx.x;
    const int t = threadIdx.x;

    if (t < MS) cnt[t] = 0;
    __syncthreads();

    const int* sb = sent_ids + (size_t)b * SS;
    for (int s = t; s < SS; s += 384) {
        int id = sb[s];
        if (id < MS) atomicAdd(&cnt[id], 1);
    }
    __syncthreads();

    const int col = t * 2;   // 384 threads x 2 floats = 768 = D

    // doc CLS rep
    float* doc = out;
    {
        float2 v = *reinterpret_cast<const float2*>(
            hidden + (size_t)b * SS * DD + col);
        *reinterpret_cast<float2*>(doc + (size_t)b * DD + col) = v;
    }

    // sent reps
    float* sreps = out + (size_t)BB * DD;
    const float* gs = g_sums + (size_t)b * MS * DD + col;
    #pragma unroll
    for (int k = 0; k < MS; k++) {
        float inv = 1.0f / fmaxf((float)cnt[k], 1.0f);
        float2 a = *reinterpret_cast<const float2*>(gs + (size_t)k * DD);
        a.x *= inv;
        a.y *= inv;
        *reinterpret_cast<float2*>(
            sreps + ((size_t)b * MS + k) * DD + col) = a;
    }
}

extern "C" void kernel_launch(void* const* d_in, const int* in_sizes, int n_in,
                              void* d_out, int out_size)
{
    const float* hidden   = (const float*)d_in[0];
    const int*   sent_ids = (const int*)d_in[1];
    float*       out      = (float*)d_out;

    zero_sums_kernel<<<(BB * MS * DD / 4 + 511) / 512, 512>>>();

    dim3 grid(DD / DC, BB, NSPLIT);   // (3, 64, 4) = 768 blocks
    accum_kernel<<<grid, NT>>>(hidden, sent_ids);

    finalize_kernel<<<BB, 384>>>(hidden, sent_ids, out);
}